// round 15
// baseline (speedup 1.0000x reference)
#include <cuda_runtime.h>
#include <cuda_bf16.h>
#include <cstdint>

// Problem constants
#define S_  2048
#define B_  4
#define D_  1024
#define H_  16
#define HD_ 64
#define NB_ 127
#define NUM_SEL_ 16
#define SEL_BLK_ 64
#define WIN_ 512
#define SCALE_ 0.125f

// ---------------- scratch (device globals; no allocation allowed) ------------
__device__ float g_qkv [8192u*3072u];   // (s*B+b, 3072)
__device__ float g_rk  [8192u*1024u];   // token-major (b*2048+s)
__device__ float g_rv  [8192u*1024u];
__device__ float g_rkm [512u*1024u];
__device__ float g_rvm [512u*1024u];
__device__ float g_padd[2048u*1024u];
__device__ float g_cmpk[512u*1024u];
__device__ float g_cmpv[512u*1024u];
__device__ float g_w1k [1024u*1024u];
__device__ float g_w1v [1024u*1024u];
__device__ float g_qm2f[8192u*128u];    // fp32 head-mean q (row s*B+b, 128 cols, 64 used)
__device__ float g_bqm [128u];
__device__ double g_ckmd[4u*127u*64u];
__device__ float g_qm1 [4u*16u*64u];
__device__ double g_qm2d[4u*2048u*64u];
__device__ float g_outcmp[4u*16u*64u];
__device__ double g_probs[4u*2048u*127u];
__device__ double g_imp [4u*127u];
__device__ int   g_seltok[4u*1024u];
__device__ float g_oslc[8192u*1024u];
__device__ float g_owin[8192u*1024u];

// bf16 digit arrays
__device__ __align__(16) __nv_bfloat16 g_xd  [3][8388608u];
__device__ __align__(16) __nv_bfloat16 g_rkmd[3][524288u];
__device__ __align__(16) __nv_bfloat16 g_rvmd[2][524288u];
__device__ __align__(16) __nv_bfloat16 g_wqkd[3][2097152u];
__device__ __align__(16) __nv_bfloat16 g_wvd [2][1048576u];
__device__ __align__(16) __nv_bfloat16 g_w1d [3][1048576u];
__device__ __align__(16) __nv_bfloat16 g_w2d [3][1048576u];
__device__ __align__(16) __nv_bfloat16 g_wkTd[3][1048576u];
__device__ __align__(16) __nv_bfloat16 g_wvTd[2][1048576u];
__device__ __align__(16) __nv_bfloat16 g_w1kd[3][1048576u];
__device__ __align__(16) __nv_bfloat16 g_w1vd[2][1048576u];
__device__ __align__(16) __nv_bfloat16 g_wqmd[3][131072u];   // 128x1024 head-mean Wq

// ---------------- warp-MMA primitives ----------------------------------------
__device__ __forceinline__ void ldsm_x4(uint32_t* r, uint32_t sa) {
    asm volatile("ldmatrix.sync.aligned.m8n8.x4.shared.b16 {%0,%1,%2,%3}, [%4];"
                 : "=r"(r[0]), "=r"(r[1]), "=r"(r[2]), "=r"(r[3]) : "r"(sa));
}
__device__ __forceinline__ void mma16816(float* c, const uint32_t* a, const uint32_t* b) {
    asm volatile("mma.sync.aligned.m16n8k16.row.col.f32.bf16.bf16.f32 "
                 "{%0,%1,%2,%3}, {%4,%5,%6,%7}, {%8,%9}, {%0,%1,%2,%3};"
                 : "+f"(c[0]), "+f"(c[1]), "+f"(c[2]), "+f"(c[3])
                 : "r"(a[0]), "r"(a[1]), "r"(a[2]), "r"(a[3]), "r"(b[0]), "r"(b[1]));
}
__device__ __forceinline__ uint32_t pack_bf2(__nv_bfloat16 a, __nv_bfloat16 b) {
    return (uint32_t)__bfloat16_as_ushort(a) | ((uint32_t)__bfloat16_as_ushort(b) << 16);
}
__device__ __forceinline__ void fsplit3(float x, __nv_bfloat16& a, __nv_bfloat16& b,
                                        __nv_bfloat16& c) {
    a = __float2bfloat16(x);
    float r = x - __bfloat162float(a);
    b = __float2bfloat16(r);
    c = __float2bfloat16(r - __bfloat162float(b));
}

// ---------------- warp-MMA GEMM ----------------------------------------------
#define TROW_B   80
#define TILE_B   (128 * TROW_B)

template<int NDIG>
__global__ __launch_bounds__(256) void mma_gemm(
    int K,
    const __nv_bfloat16* __restrict__ A0, const __nv_bfloat16* __restrict__ A1,
    const __nv_bfloat16* __restrict__ A2,
    const __nv_bfloat16* __restrict__ B0, const __nv_bfloat16* __restrict__ B1,
    const __nv_bfloat16* __restrict__ B2,
    float* __restrict__ C, int ldc,
    const float* __restrict__ colbias,
    const float* __restrict__ addmat, int addld, int relu,
    int wmode)
{
    constexpr int STAGE = 2 * NDIG * TILE_B;
    extern __shared__ char smem[];
    const int tid  = threadIdx.x;
    const int lane = tid & 31;
    const int wid  = tid >> 5;
    const int wm   = wid >> 2;
    const int wn   = wid & 3;
    const int m0   = blockIdx.y * 128;
    const int n0   = blockIdx.x * 128;

    const __nv_bfloat16* src[6] = {A0, A1, A2, B0, B1, B2};
    if (NDIG == 2) { src[2] = B0; src[3] = B1; }
    const int nk = K >> 5;

    auto load_stage = [&](int c, int s) {
#pragma unroll
        for (int it = 0; it < 4 * NDIG; it++) {
            int u   = tid + it * 256;
            int t   = u >> 9;
            int idx = u & 511;
            int row = idx >> 2, ch = idx & 3;
            const __nv_bfloat16* g = src[t]
                + (size_t)(((t < NDIG) ? m0 : n0) + row) * K + c * 32 + ch * 8;
            uint32_t sa = (uint32_t)__cvta_generic_to_shared(
                smem + s * STAGE + t * TILE_B + row * TROW_B + ch * 16);
            asm volatile("cp.async.ca.shared.global [%0], [%1], 16;" :: "r"(sa), "l"(g));
        }
        asm volatile("cp.async.commit_group;" ::: "memory");
    };

    float acc[4][4][4];
#pragma unroll
    for (int i = 0; i < 4; i++)
#pragma unroll
        for (int j = 0; j < 4; j++)
#pragma unroll
            for (int r = 0; r < 4; r++) acc[i][j][r] = 0.f;

    const int a_r  = (lane & 7) + ((lane >> 3) & 1) * 8;
    const int a_cb = (lane >> 4);
    const int b_r  = (lane & 7) + (lane >> 4) * 8;
    const int b_cb = (lane >> 3) & 1;

    load_stage(0, 0);

    for (int c = 0; c < nk; c++) {
        const int s = c & 1;
        if (c + 1 < nk) {
            load_stage(c + 1, s ^ 1);
            asm volatile("cp.async.wait_group 1;" ::: "memory");
        } else {
            asm volatile("cp.async.wait_group 0;" ::: "memory");
        }
        __syncthreads();

        const char* stg = smem + s * STAGE;
#pragma unroll
        for (int ks = 0; ks < 2; ks++) {
            uint32_t bfr[NDIG][4][2];
#pragma unroll
            for (int db = 0; db < NDIG; db++) {
                const char* tb = stg + (NDIG + db) * TILE_B;
#pragma unroll
                for (int jp = 0; jp < 2; jp++) {
                    int row = wn * 32 + jp * 16 + b_r;
                    uint32_t rr[4];
                    ldsm_x4(rr, (uint32_t)__cvta_generic_to_shared(
                        tb + row * TROW_B + (ks * 2 + b_cb) * 16));
                    bfr[db][jp * 2 + 0][0] = rr[0]; bfr[db][jp * 2 + 0][1] = rr[1];
                    bfr[db][jp * 2 + 1][0] = rr[2]; bfr[db][jp * 2 + 1][1] = rr[3];
                }
            }
#pragma unroll
            for (int da = 0; da < NDIG; da++) {
                uint32_t a[4][4];
                const char* ta = stg + da * TILE_B;
#pragma unroll
                for (int i = 0; i < 4; i++) {
                    int row = wm * 64 + i * 16 + a_r;
                    ldsm_x4(a[i], (uint32_t)__cvta_generic_to_shared(
                        ta + row * TROW_B + (ks * 2 + a_cb) * 16));
                }
#pragma unroll
                for (int db = 0; db < NDIG; db++) {
                    if (da + db >= NDIG) break;
#pragma unroll
                    for (int i = 0; i < 4; i++)
#pragma unroll
                        for (int j = 0; j < 4; j++)
                            mma16816(acc[i][j], a[i], bfr[db][j]);
                }
            }
        }
        __syncthreads();
    }

    auto emit = [&](int r, int col, float v0, float v1) {
        if (wmode == 1 || wmode == 2) {
            int h, d, co;
            if (wmode == 1) { h = col >> 7; d = col & 127; co = h * 192 + d; }
            else            { h = col >> 6; d = col & 63;  co = h * 192 + 128 + d; }
            v0 += colbias[co]; v1 += colbias[co + 1];
            *(float2*)(C + (size_t)r * 3072 + co) = make_float2(v0, v1);
            return;
        }
        if (wmode == 4) {
            int s = r >> 2, b = r & 3;
            const float* am = addmat + (size_t)s * addld + col;
            v0 = fmaxf(v0 + am[0], 0.f);
            v1 = fmaxf(v1 + am[1], 0.f);
            *(float2*)(C + (size_t)(b * 2048 + s) * 1024 + col) = make_float2(v0, v1);
            return;
        }
        if (colbias) { v0 += colbias[col]; v1 += colbias[col + 1]; }
        if (addmat) {
            const float* am = addmat + (size_t)(r & (S_ - 1)) * addld + col;
            v0 += am[0]; v1 += am[1];
        }
        if (relu) { v0 = fmaxf(v0, 0.f); v1 = fmaxf(v1, 0.f); }
        *(float2*)(C + (size_t)r * ldc + col) = make_float2(v0, v1);
    };

#pragma unroll
    for (int i = 0; i < 4; i++) {
        int row = m0 + wm * 64 + i * 16 + (lane >> 2);
#pragma unroll
        for (int j = 0; j < 4; j++) {
            int col = n0 + wn * 32 + j * 8 + (lane & 3) * 2;
            emit(row,     col, acc[i][j][0], acc[i][j][1]);
            emit(row + 8, col, acc[i][j][2], acc[i][j][3]);
        }
    }
}

// ---------------- mma flash attention (64q x 64k tiles, 2-digit bf16) --------
#define AP  72
#define ATB (64 * AP * 2)

__global__ __launch_bounds__(128) void attn_mma(
    const float* __restrict__ qkv, const int* __restrict__ seltok,
    int nkeys, int winstart, float* __restrict__ outb)
{
    extern __shared__ char smem[];
    char* Qd[2] = { smem,            smem + ATB     };
    char* Kd[2] = { smem + 2 * ATB,  smem + 3 * ATB };
    char* Vt[2] = { smem + 4 * ATB,  smem + 5 * ATB };
    char* Pd[2] = { smem + 6 * ATB,  smem + 7 * ATB };

    const int tid  = threadIdx.x;
    const int lane = tid & 31;
    const int wid  = tid >> 5;
    const int bh   = blockIdx.y;
    const int b    = bh >> 4, h = bh & 15;
    const int q0   = blockIdx.x * 64;

    const int a_r  = (lane & 7) + ((lane >> 3) & 1) * 8;
    const int a_cb = (lane >> 4);
    const int b_r  = (lane & 7) + (lane >> 4) * 8;
    const int b_cb = (lane >> 3) & 1;

#pragma unroll
    for (int i = 0; i < 8; i++) {
        int idx = tid + i * 128;
        int r = idx >> 4, ch = idx & 15;
        float4 v = *(const float4*)(qkv + (size_t)(q0 + r) * 12288 + b * 3072 + h * 192 + ch * 4);
        __nv_bfloat16 h0 = __float2bfloat16(v.x), h1 = __float2bfloat16(v.y);
        __nv_bfloat16 h2 = __float2bfloat16(v.z), h3 = __float2bfloat16(v.w);
        *(uint2*)(Qd[0] + r * (AP*2) + ch * 8) = make_uint2(pack_bf2(h0,h1), pack_bf2(h2,h3));
        __nv_bfloat16 e0 = __float2bfloat16(v.x - __bfloat162float(h0));
        __nv_bfloat16 e1 = __float2bfloat16(v.y - __bfloat162float(h1));
        __nv_bfloat16 e2 = __float2bfloat16(v.z - __bfloat162float(h2));
        __nv_bfloat16 e3 = __float2bfloat16(v.w - __bfloat162float(h3));
        *(uint2*)(Qd[1] + r * (AP*2) + ch * 8) = make_uint2(pack_bf2(e0,e1), pack_bf2(e2,e3));
    }
    __syncthreads();

    float m[2] = {-3.0e38f, -3.0e38f};
    float l[2] = {0.f, 0.f};
    float o[8][4];
#pragma unroll
    for (int j = 0; j < 8; j++)
#pragma unroll
        for (int r = 0; r < 4; r++) o[j][r] = 0.f;

    const int ntiles = nkeys >> 6;
    for (int kt = 0; kt < ntiles; kt++) {
#pragma unroll
        for (int i = 0; i < 8; i++) {
            int idx = tid + i * 128;
            int r = idx >> 4, ch = idx & 15;
            int tok = seltok ? seltok[b * 1024 + kt * 64 + r] : (winstart + kt * 64 + r);
            float4 v = *(const float4*)(qkv + (size_t)tok * 12288 + b * 3072 + h * 192 + 64 + ch * 4);
            __nv_bfloat16 h0 = __float2bfloat16(v.x), h1 = __float2bfloat16(v.y);
            __nv_bfloat16 h2 = __float2bfloat16(v.z), h3 = __float2bfloat16(v.w);
            *(uint2*)(Kd[0] + r * (AP*2) + ch * 8) = make_uint2(pack_bf2(h0,h1), pack_bf2(h2,h3));
            __nv_bfloat16 e0 = __float2bfloat16(v.x - __bfloat162float(h0));
            __nv_bfloat16 e1 = __float2bfloat16(v.y - __bfloat162float(h1));
            __nv_bfloat16 e2 = __float2bfloat16(v.z - __bfloat162float(h2));
            __nv_bfloat16 e3 = __float2bfloat16(v.w - __bfloat162float(h3));
            *(uint2*)(Kd[1] + r * (AP*2) + ch * 8) = make_uint2(pack_bf2(e0,e1), pack_bf2(e2,e3));
        }
#pragma unroll
        for (int i = 0; i < 8; i++) {
            int idx = tid + i * 128;
            int r = idx & 63, ch = idx >> 6;
            int tok = seltok ? seltok[b * 1024 + kt * 64 + r] : (winstart + kt * 64 + r);
            float4 v = *(const float4*)(qkv + (size_t)tok * 12288 + b * 3072 + h * 192 + 128 + ch * 4);
            float vv[4] = {v.x, v.y, v.z, v.w};
#pragma unroll
            for (int jj = 0; jj < 4; jj++) {
                __nv_bfloat16 h0 = __float2bfloat16(vv[jj]);
                __nv_bfloat16 e0 = __float2bfloat16(vv[jj] - __bfloat162float(h0));
                *(__nv_bfloat16*)(Vt[0] + (ch * 4 + jj) * (AP*2) + r * 2) = h0;
                *(__nv_bfloat16*)(Vt[1] + (ch * 4 + jj) * (AP*2) + r * 2) = e0;
            }
        }
        __syncthreads();

        float sc[8][4];
#pragma unroll
        for (int j = 0; j < 8; j++)
#pragma unroll
            for (int r = 0; r < 4; r++) sc[j][r] = 0.f;

#pragma unroll
        for (int pr = 0; pr < 3; pr++) {
            const int da = (pr == 2) ? 1 : 0;
            const int db = (pr == 1) ? 1 : 0;
#pragma unroll
            for (int ks = 0; ks < 4; ks++) {
                uint32_t a[4];
                ldsm_x4(a, (uint32_t)__cvta_generic_to_shared(
                    Qd[da] + (wid * 16 + a_r) * (AP*2) + (ks * 2 + a_cb) * 16));
                uint32_t bb[8][2];
#pragma unroll
                for (int jp = 0; jp < 4; jp++) {
                    uint32_t rr[4];
                    ldsm_x4(rr, (uint32_t)__cvta_generic_to_shared(
                        Kd[db] + (jp * 16 + b_r) * (AP*2) + (ks * 2 + b_cb) * 16));
                    bb[jp*2+0][0] = rr[0]; bb[jp*2+0][1] = rr[1];
                    bb[jp*2+1][0] = rr[2]; bb[jp*2+1][1] = rr[3];
                }
#pragma unroll
                for (int j = 0; j < 8; j++) mma16816(sc[j], a, bb[j]);
            }
        }

        float mx0 = -3.0e38f, mx1 = -3.0e38f;
#pragma unroll
        for (int j = 0; j < 8; j++) {
#pragma unroll
            for (int r = 0; r < 4; r++) sc[j][r] *= SCALE_;
            mx0 = fmaxf(mx0, fmaxf(sc[j][0], sc[j][1]));
            mx1 = fmaxf(mx1, fmaxf(sc[j][2], sc[j][3]));
        }
        mx0 = fmaxf(mx0, __shfl_xor_sync(0xffffffffu, mx0, 1));
        mx0 = fmaxf(mx0, __shfl_xor_sync(0xffffffffu, mx0, 2));
        mx1 = fmaxf(mx1, __shfl_xor_sync(0xffffffffu, mx1, 1));
        mx1 = fmaxf(mx1, __shfl_xor_sync(0xffffffffu, mx1, 2));
        float mn0 = fmaxf(m[0], mx0), mn1 = fmaxf(m[1], mx1);
        float corr0 = __expf(m[0] - mn0), corr1 = __expf(m[1] - mn1);

        const int prow0 = wid * 16 + (lane >> 2);
        const int pcol  = (lane & 3) * 2;
        float sum0 = 0.f, sum1 = 0.f;
#pragma unroll
        for (int j = 0; j < 8; j++) {
            float p00 = __expf(sc[j][0] - mn0);
            float p01 = __expf(sc[j][1] - mn0);
            float p10 = __expf(sc[j][2] - mn1);
            float p11 = __expf(sc[j][3] - mn1);
            sum0 += p00 + p01; sum1 += p10 + p11;
            __nv_bfloat16 a0 = __float2bfloat16(p00), a1 = __float2bfloat16(p01);
            __nv_bfloat16 b0 = __float2bfloat16(p10), b1 = __float2bfloat16(p11);
            int c0 = j * 8 + pcol;
            *(uint32_t*)(Pd[0] + prow0 * (AP*2) + c0 * 2)       = pack_bf2(a0, a1);
            *(uint32_t*)(Pd[0] + (prow0 + 8) * (AP*2) + c0 * 2) = pack_bf2(b0, b1);
            __nv_bfloat16 ae0 = __float2bfloat16(p00 - __bfloat162float(a0));
            __nv_bfloat16 ae1 = __float2bfloat16(p01 - __bfloat162float(a1));
            __nv_bfloat16 be0 = __float2bfloat16(p10 - __bfloat162float(b0));
            __nv_bfloat16 be1 = __float2bfloat16(p11 - __bfloat162float(b1));
            *(uint32_t*)(Pd[1] + prow0 * (AP*2) + c0 * 2)       = pack_bf2(ae0, ae1);
            *(uint32_t*)(Pd[1] + (prow0 + 8) * (AP*2) + c0 * 2) = pack_bf2(be0, be1);
        }
        sum0 += __shfl_xor_sync(0xffffffffu, sum0, 1);
        sum0 += __shfl_xor_sync(0xffffffffu, sum0, 2);
        sum1 += __shfl_xor_sync(0xffffffffu, sum1, 1);
        sum1 += __shfl_xor_sync(0xffffffffu, sum1, 2);
        l[0] = l[0] * corr0 + sum0; m[0] = mn0;
        l[1] = l[1] * corr1 + sum1; m[1] = mn1;
#pragma unroll
        for (int j = 0; j < 8; j++) {
            o[j][0] *= corr0; o[j][1] *= corr0;
            o[j][2] *= corr1; o[j][3] *= corr1;
        }
        __syncthreads();

#pragma unroll
        for (int pr = 0; pr < 3; pr++) {
            const int da = (pr == 2) ? 1 : 0;
            const int db = (pr == 1) ? 1 : 0;
#pragma unroll
            for (int ks = 0; ks < 4; ks++) {
                uint32_t a[4];
                ldsm_x4(a, (uint32_t)__cvta_generic_to_shared(
                    Pd[da] + (wid * 16 + a_r) * (AP*2) + (ks * 2 + a_cb) * 16));
                uint32_t bb[8][2];
#pragma unroll
                for (int jp = 0; jp < 4; jp++) {
                    uint32_t rr[4];
                    ldsm_x4(rr, (uint32_t)__cvta_generic_to_shared(
                        Vt[db] + (jp * 16 + b_r) * (AP*2) + (ks * 2 + b_cb) * 16));
                    bb[jp*2+0][0] = rr[0]; bb[jp*2+0][1] = rr[1];
                    bb[jp*2+1][0] = rr[2]; bb[jp*2+1][1] = rr[3];
                }
#pragma unroll
                for (int j = 0; j < 8; j++) mma16816(o[j], a, bb[j]);
            }
        }
        __syncthreads();
    }

    const float inv0 = 1.f / l[0], inv1 = 1.f / l[1];
    const int row0 = q0 + wid * 16 + (lane >> 2);
#pragma unroll
    for (int j = 0; j < 8; j++) {
        int col = h * 64 + j * 8 + (lane & 3) * 2;
        *(float2*)(outb + (size_t)(b * S_ + row0) * 1024 + col) =
            make_float2(o[j][0] * inv0, o[j][1] * inv0);
        *(float2*)(outb + (size_t)(b * S_ + row0 + 8) * 1024 + col) =
            make_float2(o[j][2] * inv1, o[j][3] * inv1);
    }
}

// ---------------- split / prep kernels ---------------------------------------
__global__ void split3k(const float* __restrict__ s,
                        __nv_bfloat16* __restrict__ d0, __nv_bfloat16* __restrict__ d1,
                        __nv_bfloat16* __restrict__ d2, int n)
{
    int i = blockIdx.x * 256 + threadIdx.x;
    if (i >= n) return;
    __nv_bfloat16 a, b, c;
    fsplit3(s[i], a, b, c);
    d0[i] = a; d1[i] = b; d2[i] = c;
}

__global__ void split2k(const float* __restrict__ s,
                        __nv_bfloat16* __restrict__ d0, __nv_bfloat16* __restrict__ d1, int n)
{
    int i = blockIdx.x * 256 + threadIdx.x;
    if (i >= n) return;
    float x = s[i];
    __nv_bfloat16 a = __float2bfloat16(x);
    d0[i] = a;
    d1[i] = __float2bfloat16(x - __bfloat162float(a));
}

__global__ void prep_wqk(const float* __restrict__ w_qkv)
{
    int idx = blockIdx.x * 256 + threadIdx.x;
    int r = idx >> 10, k = idx & 1023;
    int h = r >> 7, d = r & 127;
    float x = w_qkv[(size_t)(h * 192 + d) * 1024 + k];
    __nv_bfloat16 a, b, c;
    fsplit3(x, a, b, c);
    g_wqkd[0][idx] = a; g_wqkd[1][idx] = b; g_wqkd[2][idx] = c;
}

// head-mean of Wq rows (128x1024; rows 64.. are zero) for the qm2 GEMM
__global__ void prep_wqm(const float* __restrict__ w_qkv)
{
    int idx = blockIdx.x * 256 + threadIdx.x;     // 128*1024
    if (idx >= 131072) return;
    int d = idx >> 10, k = idx & 1023;
    float v = 0.f;
    if (d < 64) {
#pragma unroll
        for (int h = 0; h < H_; h++) v += w_qkv[(size_t)(h * 192 + d) * 1024 + k];
        v *= (1.f / (float)H_);
    }
    __nv_bfloat16 a, b, c;
    fsplit3(v, a, b, c);
    g_wqmd[0][idx] = a; g_wqmd[1][idx] = b; g_wqmd[2][idx] = c;
}

__global__ void prep_bqm(const float* __restrict__ b_qkv)
{
    int d = threadIdx.x;        // 128
    float v = 0.f;
    if (d < 64) {
#pragma unroll
        for (int h = 0; h < H_; h++) v += b_qkv[h * 192 + d];
        v *= (1.f / (float)H_);
    }
    g_bqm[d] = v;
}

__global__ void qm2cvt()
{
    int idx = blockIdx.x * 256 + threadIdx.x;     // 8192*64
    if (idx >= 8192 * 64) return;
    int r = idx >> 6, d = idx & 63;
    int s = r >> 2, b = r & 3;
    g_qm2d[((size_t)(b * 2048 + s)) * 64 + d] = (double)g_qm2f[(size_t)r * 128 + d];
}

__global__ void prep_wv(const float* __restrict__ w_qkv)
{
    int idx = blockIdx.x * 256 + threadIdx.x;
    int r = idx >> 10, k = idx & 1023;
    int h = r >> 6, d = r & 63;
    float x = w_qkv[(size_t)(h * 192 + 128 + d) * 1024 + k];
    __nv_bfloat16 a = __float2bfloat16(x);
    g_wvd[0][idx] = a;
    g_wvd[1][idx] = __float2bfloat16(x - __bfloat162float(a));
}

__global__ __launch_bounds__(256) void prep_wkT(const float* __restrict__ w_qkv)
{
    __shared__ float tile[32][33];
    int cb = blockIdx.x * 32, db = blockIdx.y * 32;
    int tx = threadIdx.x & 31, ty = threadIdx.x >> 5;
    for (int i = ty; i < 32; i += 8) {
        int d = db + i, h = d >> 6, dd = d & 63;
        tile[i][tx] = w_qkv[(size_t)(h * 192 + 64 + dd) * 1024 + cb + tx];
    }
    __syncthreads();
    for (int i = ty; i < 32; i += 8) {
        int c = cb + i, d = db + tx;
        __nv_bfloat16 a, b, cc;
        fsplit3(tile[tx][i], a, b, cc);
        size_t off = (size_t)c * 1024 + d;
        g_wkTd[0][off] = a; g_wkTd[1][off] = b; g_wkTd[2][off] = cc;
    }
}

__global__ __launch_bounds__(256) void prep_wvT(const float* __restrict__ w_qkv)
{
    __shared__ float tile[32][33];
    int cb = blockIdx.x * 32, db = blockIdx.y * 32;
    int tx = threadIdx.x & 31, ty = threadIdx.x >> 5;
    for (int i = ty; i < 32; i += 8) {
        int d = db + i, h = d >> 6, dd = d & 63;
        tile[i][tx] = w_qkv[(size_t)(h * 192 + 128 + dd) * 1024 + cb + tx];
    }
    __syncthreads();
    for (int i = ty; i < 32; i += 8) {
        int c = cb + i, d = db + tx;
        float x = tile[tx][i];
        __nv_bfloat16 a = __float2bfloat16(x);
        size_t off = (size_t)c * 1024 + d;
        g_wvTd[0][off] = a;
        g_wvTd[1][off] = __float2bfloat16(x - __bfloat162float(a));
    }
}

__global__ void prep_w1d(const float* __restrict__ w_c1)
{
    int idx = blockIdx.x * 256 + threadIdx.x;
    int n = idx >> 10, k = idx & 1023;
    __nv_bfloat16 a, b, c;
    fsplit3(w_c1[n * 1027 + k], a, b, c);
    g_w1d[0][idx] = a; g_w1d[1][idx] = b; g_w1d[2][idx] = c;
}

__global__ void prep_padd(const float* __restrict__ w_c1,
                          const float* __restrict__ b_c1,
                          const float* __restrict__ pos)
{
    int idx = blockIdx.x * 256 + threadIdx.x;
    int s = idx >> 10, n = idx & 1023;
    const float* wr = w_c1 + n * 1027 + 1024;
    g_padd[idx] = b_c1[n] + wr[0]*pos[s*3] + wr[1]*pos[s*3+1] + wr[2]*pos[s*3+2];
}

// ---------------- aux kernels -------------------------------------------------
__global__ void cmp_reduce_one(const float* __restrict__ src, float* __restrict__ dst)
{
    int idx = blockIdx.x * 256 + threadIdx.x;
    if (idx >= B_ * NB_ * 1024) return;
    int c = idx & 1023;
    int n = (idx >> 10) % NB_;
    int b = idx / (NB_ * 1024);
    float s = 0.f;
    size_t base = (size_t)(b * S_ + n * 16) * 1024 + c;
#pragma unroll 8
    for (int j = 0; j < 32; j++) s += src[base + (size_t)j * 1024];
    dst[(size_t)(b * NB_ + n) * 1024 + c] = s * (1.f / 32.f);
}

__global__ __launch_bounds__(256) void calc_qm1(const float* __restrict__ qkv)
{
    int bh = blockIdx.x;
    int b = bh >> 4, h = bh & 15;
    int tid = threadIdx.x;
    int strip = tid >> 6, d = tid & 63;
    float a = 0.f;
    size_t off = (size_t)b * 3072 + h * 192 + d;
    for (int t = strip * 512; t < (strip + 1) * 512; t++)
        a += qkv[(size_t)t * 12288 + off];
    __shared__ float red[256];
    red[tid] = a; __syncthreads();
    if (strip == 0)
        g_qm1[bh * 64 + d] = (red[d] + red[64 + d] + red[128 + d] + red[192 + d])
                             * (1.f / (float)S_);
}

__global__ void calc_ckm()
{
    int idx = blockIdx.x * 256 + threadIdx.x;
    if (idx >= B_ * NB_ * 64) return;
    int d = idx & 63;
    int n = (idx >> 6) % NB_;
    int b = idx / (NB_ * 64);
    double a = 0.0;
    size_t base = (size_t)(b * NB_ + n) * 1024 + d;
#pragma unroll
    for (int h = 0; h < H_; h++) a += (double)g_cmpk[base + h * 64];
    g_ckmd[idx] = a * (1.0 / (double)H_);
}

__global__ __launch_bounds__(128) void outcmp_kernel()
{
    int bh = blockIdx.x;
    int b = bh >> 4, h = bh & 15;
    int tid = threadIdx.x;
    __shared__ float qs[64], p[128], red[128];
    if (tid < 64) qs[tid] = g_qm1[bh * 64 + tid];
    __syncthreads();
    float sc = -3.0e38f;
    if (tid < NB_) {
        const float* kr = &g_cmpk[(size_t)(b * NB_ + tid) * 1024 + h * 64];
        float dot = 0.f;
#pragma unroll
        for (int d = 0; d < 64; d++) dot += qs[d] * kr[d];
        sc = dot * SCALE_;
    }
    red[tid] = sc; __syncthreads();
    for (int off = 64; off; off >>= 1) { if (tid < off) red[tid] = fmaxf(red[tid], red[tid + off]); __syncthreads(); }
    float mx = red[0]; __syncthreads();
    float e = (tid < NB_) ? __expf(sc - mx) : 0.f;
    p[tid] = e;
    red[tid] = e; __syncthreads();
    for (int off = 64; off; off >>= 1) { if (tid < off) red[tid] += red[tid + off]; __syncthreads(); }
    float inv = 1.f / red[0];
    if (tid < 64) {
        float a = 0.f;
        for (int n = 0; n < NB_; n++)
            a += p[n] * g_cmpv[(size_t)(b * NB_ + n) * 1024 + h * 64 + tid];
        g_outcmp[bh * 64 + tid] = a * inv;
    }
}

__global__ __launch_bounds__(128) void imp_probs8()
{
    extern __shared__ double sh[];
    double* cks = sh;
    double* qs  = sh + 127 * 65;
    __shared__ double red[128];
    const int b  = blockIdx.y;
    const int s0 = blockIdx.x * 8;
    const int tid = threadIdx.x;

    for (int i = tid; i < NB_ * 64; i += 128) {
        int n = i >> 6, d = i & 63;
        cks[n * 65 + d] = g_ckmd[((size_t)b * NB_ + n) * 64 + d];
    }
    for (int i = tid; i < 8 * 64; i += 128)
        qs[i] = g_qm2d[((size_t)(b * 2048 + s0)) * 64 + i];
    __syncthreads();

    for (int ss = 0; ss < 8; ss++) {
        double sc = -1.0e300;
        if (tid < NB_) {
            const double* kr = &cks[tid * 65];
            const double* qq = &qs[ss * 64];
            double dot = 0.0;
#pragma unroll
            for (int d = 0; d < 64; d++) dot += qq[d] * kr[d];
            sc = dot * 0.125;
        }
        red[tid] = sc; __syncthreads();
        for (int off = 64; off; off >>= 1) { if (tid < off) red[tid] = fmax(red[tid], red[tid + off]); __syncthreads(); }
        double mx = red[0]; __syncthreads();
        double e = (tid < NB_) ? exp(sc - mx) : 0.0;
        red[tid] = e; __syncthreads();
        for (int off = 64; off; off >>= 1) { if (tid < off) red[tid] += red[tid + off]; __syncthreads(); }
        double inv = 1.0 / red[0];
        if (tid < NB_) g_probs[((size_t)(b * 2048 + s0 + ss)) * NB_ + tid] = e * inv;
        __syncthreads();
    }
}

__global__ __launch_bounds__(128) void imp_reduce()
{
    int blk = blockIdx.x;
    if (blk >= B_ * NB_) return;
    int b = blk / NB_, n = blk % NB_;
    int tid = threadIdx.x;
    __shared__ double red[128];
    double a = 0.0;
    for (int s = tid; s < S_; s += 128)
        a += g_probs[(size_t)(b * S_ + s) * NB_ + n];
    red[tid] = a; __syncthreads();
    for (int off = 64; off; off >>= 1) {
        if (tid < off) red[tid] += red[tid + off];
        __syncthreads();
    }
    if (tid == 0) g_imp[blk] = red[0] * (1.0 / (double)S_);
}

__global__ __launch_bounds__(128) void topk_sel()
{
    int b = blockIdx.x, tid = threadIdx.x;
    __shared__ double vals[NB_];
    __shared__ int    sb[NUM_SEL_];
    if (tid < NB_) vals[tid] = g_imp[b * NB_ + tid];
    __syncthreads();
    if (tid == 0) {
        for (int i = 0; i < NUM_SEL_; i++) {
            int bi = 0; double bv = vals[0];
            for (int n = 1; n < NB_; n++) if (vals[n] > bv) { bv = vals[n]; bi = n; }
            sb[i] = bi; vals[bi] = -1.0e300;
        }
    }
    __syncthreads();
    for (int j = tid; j < NUM_SEL_ * SEL_BLK_; j += 128) {
        int t = sb[j >> 6] * SEL_BLK_ + (j & 63);
        if (t > S_ - 1) t = S_ - 1;
        g_seltok[b * 1024 + j] = t;
    }
}

__global__ __launch_bounds__(128) void gate_combine(
    const float* __restrict__ w_g, const float* __restrict__ b_g,
    float* __restrict__ out)
{
    int bs = blockIdx.x;
    int b = bs >> 11;
    int tid = threadIdx.x;
    size_t base = (size_t)bs * 1024;
    float a0 = 0.f, a1 = 0.f, a2 = 0.f;
    for (int c = tid; c < 3072; c += 128) {
        float v;
        if (c < 1024)       v = g_outcmp[(b * 16 + (c >> 6)) * 64 + (c & 63)];
        else if (c < 2048)  v = g_oslc[base + c - 1024];
        else                v = g_owin[base + c - 2048];
        a0 += v * w_g[c];
        a1 += v * w_g[3072 + c];
        a2 += v * w_g[6144 + c];
    }
    __shared__ float r0[128], r1[128], r2[128];
    __shared__ float gg[3];
    r0[tid] = a0; r1[tid] = a1; r2[tid] = a2; __syncthreads();
    for (int off = 64; off; off >>= 1) {
        if (tid < off) { r0[tid] += r0[tid+off]; r1[tid] += r1[tid+off]; r2[tid] += r2[tid+off]; }
        __syncthreads();
    }
    if (tid == 0) {
        float l0 = r0[0] + b_g[0], l1 = r1[0] + b_g[1], l2 = r2[0] + b_g[2];
        float mx = fmaxf(l0, fmaxf(l1, l2));
        float e0 = __expf(l0 - mx), e1 = __expf(l1 - mx), e2 = __expf(l2 - mx);
        float inv = 1.f / (e0 + e1 + e2);
        gg[0] = e0 * inv; gg[1] = e1 * inv; gg[2] = e2 * inv;
    }
    __syncthreads();
    float gv0 = gg[0], gv1 = gg[1], gv2 = gg[2];
    for (int c = tid; c < 1024; c += 128) {
        float oc = g_outcmp[(b * 16 + (c >> 6)) * 64 + (c & 63)];
        out[base + c] = gv0 * oc + gv1 * g_oslc[base + c] + gv2 * g_owin[base + c];
    }
}

// ---------------- launch -----------------------------------------------------
extern "C" void kernel_launch(void* const* d_in, const int* in_sizes, int n_in,
                              void* d_out, int out_size)
{
    const float* x     = (const float*)d_in[0];
    const float* pos   = (const float*)d_in[1];
    const float* w_qkv = (const float*)d_in[2];
    const float* b_qkv = (const float*)d_in[3];
    const float* w_c1  = (const float*)d_in[4];
    const float* b_c1  = (const float*)d_in[5];
    const float* w_c2  = (const float*)d_in[6];
    const float* b_c2  = (const float*)d_in[7];
    const float* w_g   = (const float*)d_in[8];
    const float* b_g   = (const float*)d_in[9];
    float* out = (float*)d_out;
    (void)in_sizes; (void)n_in; (void)out_size;

    void *p_qkv, *p_padd, *p_sel, *p_oslc, *p_owin, *p_rk, *p_rv, *p_rkm, *p_rvm;
    void *p_cmpk, *p_cmpv, *p_w1k, *p_w1v, *p_qm2f, *p_bqm;
    cudaGetSymbolAddress(&p_qkv,  g_qkv);
    cudaGetSymbolAddress(&p_padd, g_padd);
    cudaGetSymbolAddress(&p_sel,  g_seltok);
    cudaGetSymbolAddress(&p_oslc, g_oslc);
    cudaGetSymbolAddress(&p_owin, g_owin);
    cudaGetSymbolAddress(&p_rk,   g_rk);
    cudaGetSymbolAddress(&p_rv,   g_rv);
    cudaGetSymbolAddress(&p_rkm,  g_rkm);
    cudaGetSymbolAddress(&p_rvm,  g_rvm);
    cudaGetSymbolAddress(&p_cmpk, g_cmpk);
    cudaGetSymbolAddress(&p_cmpv, g_cmpv);
    cudaGetSymbolAddress(&p_w1k,  g_w1k);
    cudaGetSymbolAddress(&p_w1v,  g_w1v);
    cudaGetSymbolAddress(&p_qm2f, g_qm2f);
    cudaGetSymbolAddress(&p_bqm,  g_bqm);

    void *p_xd, *p_rkmd, *p_rvmd, *p_wqkd, *p_wvd, *p_w1d, *p_w2d;
    void *p_wkTd, *p_wvTd, *p_w1kd, *p_w1vd, *p_wqmd;
    cudaGetSymbolAddress(&p_xd,   g_xd);
    cudaGetSymbolAddress(&p_rkmd, g_rkmd);
    cudaGetSymbolAddress(&p_rvmd, g_rvmd);
    cudaGetSymbolAddress(&p_wqkd, g_wqkd);
    cudaGetSymbolAddress(&p_wvd,  g_wvd);
    cudaGetSymbolAddress(&p_w1d,  g_w1d);
    cudaGetSymbolAddress(&p_w2d,  g_w2d);
    cudaGetSymbolAddress(&p_wkTd, g_wkTd);
    cudaGetSymbolAddress(&p_wvTd, g_wvTd);
    cudaGetSymbolAddress(&p_w1kd, g_w1kd);
    cudaGetSymbolAddress(&p_w1vd, g_w1vd);
    cudaGetSymbolAddress(&p_wqmd, g_wqmd);

    const size_t BIGN = 8388608u;
    const size_t WQKN = 2097152u;
    const size_t WN   = 1048576u;
    const size_t RMN  = 524288u;
    const size_t WQMN = 131072u;
    __nv_bfloat16* xd   = (__nv_bfloat16*)p_xd;
    __nv_bfloat16* rkmd = (__nv_bfloat16*)p_rkmd;
    __nv_bfloat16* rvmd = (__nv_bfloat16*)p_rvmd;
    __nv_bfloat16* wqkd = (__nv_bfloat16*)p_wqkd;
    __nv_bfloat16* wvd  = (__nv_bfloat16*)p_wvd;
    __nv_bfloat16* w1d  = (__nv_bfloat16*)p_w1d;
    __nv_bfloat16* w2d  = (__nv_bfloat16*)p_w2d;
    __nv_bfloat16* wkTd = (__nv_bfloat16*)p_wkTd;
    __nv_bfloat16* wvTd = (__nv_bfloat16*)p_wvTd;
    __nv_bfloat16* w1kd = (__nv_bfloat16*)p_w1kd;
    __nv_bfloat16* w1vd = (__nv_bfloat16*)p_w1vd;
    __nv_bfloat16* wqmd = (__nv_bfloat16*)p_wqmd;

    const int GS3 = 2 * 6 * TILE_B;
    const int GS2 = 2 * 4 * TILE_B;
    const int ASM = 8 * ATB;
    const int IPS = (127 * 65 + 8 * 64) * 8;
    cudaFuncSetAttribute(mma_gemm<3>, cudaFuncAttributeMaxDynamicSharedMemorySize, GS3);
    cudaFuncSetAttribute(mma_gemm<2>, cudaFuncAttributeMaxDynamicSharedMemorySize, GS2);
    cudaFuncSetAttribute(attn_mma, cudaFuncAttributeMaxDynamicSharedMemorySize, ASM);
    cudaFuncSetAttribute(imp_probs8, cudaFuncAttributeMaxDynamicSharedMemorySize, IPS);

    static cudaStream_t sA = nullptr, sB = nullptr, sC = nullptr;
    static cudaEvent_t e0 = nullptr, eX = nullptr, e1 = nullptr, eV = nullptr,
                       eQm = nullptr, eCk = nullptr, eWin = nullptr, eOc = nullptr,
                       eW1d = nullptr;
    if (!sA) {
        cudaStreamCreateWithFlags(&sA, cudaStreamNonBlocking);
        cudaStreamCreateWithFlags(&sB, cudaStreamNonBlocking);
        cudaStreamCreateWithFlags(&sC, cudaStreamNonBlocking);
        cudaEventCreateWithFlags(&e0,   cudaEventDisableTiming);
        cudaEventCreateWithFlags(&eX,   cudaEventDisableTiming);
        cudaEventCreateWithFlags(&e1,   cudaEventDisableTiming);
        cudaEventCreateWithFlags(&eV,   cudaEventDisableTiming);
        cudaEventCreateWithFlags(&eQm,  cudaEventDisableTiming);
        cudaEventCreateWithFlags(&eCk,  cudaEventDisableTiming);
        cudaEventCreateWithFlags(&eWin, cudaEventDisableTiming);
        cudaEventCreateWithFlags(&eOc,  cudaEventDisableTiming);
        cudaEventCreateWithFlags(&eW1d, cudaEventDisableTiming);
    }

    // fork root
    cudaEventRecord(e0, 0);

    // s0: x split, qk projection (3-product), qm chain
    split3k<<<32768, 256>>>(x, xd, xd + BIGN, xd + 2*BIGN, 8388608);
    cudaEventRecord(eX, 0);
    prep_wqk<<<8192, 256>>>(w_qkv);
    prep_wqm<<<512, 256>>>(w_qkv);
    prep_bqm<<<1, 128>>>(b_qkv);
    mma_gemm<2><<<dim3(16, 64), 256, GS2>>>(1024,
        xd, xd + BIGN, nullptr,
        wqkd, wqkd + WQKN, nullptr,
        (float*)p_qkv, 3072, b_qkv, nullptr, 0, 0, 1);
    cudaEventRecord(e1, 0);
    calc_qm1<<<64, 256>>>((const float*)p_qkv);
    // qm2 via exact head-mean fold: x @ Wqm^T (6-product) -> fp64 convert
    mma_gemm<3><<<dim3(1, 64), 256, GS3>>>(1024,
        xd, xd + BIGN, xd + 2*BIGN,
        wqmd, wqmd + WQMN, wqmd + 2*WQMN,
        (float*)p_qm2f, 128, (const float*)p_bqm, nullptr, 0, 0, 0);
    qm2cvt<<<2048, 256>>>();
    cudaEventRecord(eQm, 0);

    // sB: weight prep -> W1K -> fused k-L1 chain -> ckm
    cudaStreamWaitEvent(sB, e0, 0);
    prep_padd<<<8192, 256, 0, sB>>>(w_c1, b_c1, pos);
    prep_w1d<<<4096, 256, 0, sB>>>(w_c1);
    split3k<<<4096, 256, 0, sB>>>(w_c2, w2d, w2d + WN, w2d + 2*WN, 1048576);
    cudaEventRecord(eW1d, sB);
    prep_wkT<<<dim3(32, 32), 256, 0, sB>>>(w_qkv);
    mma_gemm<3><<<dim3(8, 8), 256, GS3, sB>>>(1024,
        w1d, w1d + WN, w1d + 2*WN,
        wkTd, wkTd + WN, wkTd + 2*WN,
        (float*)p_w1k, 1024, nullptr, nullptr, 0, 0, 0);
    split3k<<<4096, 256, 0, sB>>>((const float*)p_w1k, w1kd, w1kd + WN, w1kd + 2*WN, 1048576);
    cudaStreamWaitEvent(sB, eX, 0);
    mma_gemm<3><<<dim3(8, 64), 256, GS3, sB>>>(1024,
        xd, xd + BIGN, xd + 2*BIGN,
        w1kd, w1kd + WN, w1kd + 2*WN,
        (float*)p_rk, 1024, nullptr, (const float*)p_padd, 1024, 1, 4);
    cmp_reduce_one<<<2032, 256, 0, sB>>>((const float*)p_rk, (float*)p_rkm);
    split3k<<<2048, 256, 0, sB>>>((const float*)p_rkm, rkmd, rkmd + RMN, rkmd + 2*RMN, 524288);
    mma_gemm<3><<<dim3(8, 4), 256, GS3, sB>>>(1024,
        rkmd, rkmd + RMN, rkmd + 2*RMN,
        w2d, w2d + WN, w2d + 2*WN,
        (float*)p_cmpk, 1024, b_c2, nullptr, 0, 0, 0);
    calc_ckm<<<127, 256, 0, sB>>>();
    cudaEventRecord(eCk, sB);

    // sC: v projection + fused v-L1 chain + outcmp
    cudaStreamWaitEvent(sC, e0, 0);
    prep_wv <<<4096, 256, 0, sC>>>(w_qkv);
    prep_wvT<<<dim3(32, 32), 256, 0, sC>>>(w_qkv);
    cudaStreamWaitEvent(sC, eX, 0);
    mma_gemm<2><<<dim3(8, 64), 256, GS2, sC>>>(1024,
        xd, xd + BIGN, nullptr,
        wvd, wvd + WN, nullptr,
        (float*)p_qkv, 3072, b_qkv, nullptr, 0, 0, 2);
    cudaEventRecord(eV, sC);
    cudaStreamWaitEvent(sC, eW1d, 0);
    mma_gemm<2><<<dim3(8, 8), 256, GS2, sC>>>(1024,
        w1d, w1d + WN, nullptr,
        wvTd, wvTd + WN, nullptr,
        (float*)p_w1v, 1024, nullptr, nullptr, 0, 0, 0);
    split2k<<<4096, 256, 0, sC>>>((const float*)p_w1v, w1vd, w1vd + WN, 1048576);
    mma_gemm<2><<<dim3(8, 64), 256, GS2, sC>>>(1024,
        xd, xd + BIGN, nullptr,
        w1vd, w1vd + WN, nullptr,
        (float*)p_rv, 1024, nullptr, (const float*)p_padd, 1024, 1, 4);
    cmp_reduce_one<<<2032, 256, 0, sC>>>((const float*)p_rv, (float*)p_rvm);
    split2k<<<2048, 256, 0, sC>>>((const float*)p_rvm, rvmd, rvmd + RMN, 524288);
    mma_gemm<2><<<dim3(8, 4), 256, GS2, sC>>>(1024,
        rvmd, rvmd + RMN, nullptr,
        w2d, w2d + WN, nullptr,
        (float*)p_cmpv, 1024, b_c2, nullptr, 0, 0, 0);
    cudaStreamWaitEvent(sC, eCk, 0);
    cudaStreamWaitEvent(sC, e1, 0);
    outcmp_kernel<<<64, 128, 0, sC>>>();
    cudaEventRecord(eOc, sC);

    // sA: window attention (needs q,k + v cols)
    cudaStreamWaitEvent(sA, e1, 0);
    cudaStreamWaitEvent(sA, eV, 0);
    attn_mma<<<dim3(S_ / 64, B_ * H_), 128, ASM, sA>>>(
        (const float*)p_qkv, nullptr, WIN_, S_ - WIN_, (float*)p_owin);
    cudaEventRecord(eWin, sA);

    // s0: importance -> top-k -> selected attention
    cudaStreamWaitEvent((cudaStream_t)0, eCk, 0);
    imp_probs8<<<dim3(256, B_), 128, IPS>>>();
    imp_reduce<<<B_ * NB_, 128>>>();
    topk_sel<<<4, 128>>>();
    cudaStreamWaitEvent((cudaStream_t)0, eV, 0);
    attn_mma<<<dim3(S_ / 64, B_ * H_), 128, ASM>>>(
        (const float*)p_qkv, (const int*)p_sel, 1024, 0, (float*)p_oslc);

    // join everything, gate
    cudaStreamWaitEvent((cudaStream_t)0, eWin, 0);
    cudaStreamWaitEvent((cudaStream_t)0, eOc, 0);
    gate_combine<<<8192, 128>>>(w_g, b_g, out);
}

// round 16
// speedup vs baseline: 1.5689x; 1.5689x over previous
#include <cuda_runtime.h>
#include <cuda_bf16.h>
#include <cstdint>

// Problem constants
#define S_  2048
#define B_  4
#define D_  1024
#define H_  16
#define HD_ 64
#define NB_ 127
#define NUM_SEL_ 16
#define SEL_BLK_ 64
#define WIN_ 512
#define SCALE_ 0.125f

// ---------------- scratch (device globals; no allocation allowed) ------------
__device__ float g_qkv [8192u*3072u];   // (s*B+b, 3072)
__device__ float g_rk  [8192u*1024u];   // token-major (b*2048+s)
__device__ float g_rv  [8192u*1024u];
__device__ float g_rkm [512u*1024u];
__device__ float g_rvm [512u*1024u];
__device__ float g_padd[2048u*1024u];
__device__ float g_cmpk[512u*1024u];
__device__ float g_cmpv[512u*1024u];
__device__ float g_w1k [1024u*1024u];
__device__ float g_w1v [1024u*1024u];
__device__ float g_qm2f[8192u*128u];
__device__ float g_bqm [128u];
__device__ double g_ckmd[4u*127u*64u];
__device__ float g_qm1 [4u*16u*64u];
__device__ double g_qm2d[4u*2048u*64u];
__device__ float g_outcmp[4u*16u*64u];
__device__ double g_probs[4u*2048u*127u];
__device__ double g_imp [4u*127u];
__device__ int   g_seltok[4u*1024u];
__device__ float g_oslc[8192u*1024u];
__device__ float g_owin[8192u*1024u];

// bf16 digit arrays
__device__ __align__(16) __nv_bfloat16 g_xd  [3][8388608u];
__device__ __align__(16) __nv_bfloat16 g_rkmd[3][524288u];
__device__ __align__(16) __nv_bfloat16 g_rvmd[2][524288u];
__device__ __align__(16) __nv_bfloat16 g_wqkd[3][2097152u];
__device__ __align__(16) __nv_bfloat16 g_wvd [2][1048576u];
__device__ __align__(16) __nv_bfloat16 g_w1d [3][1048576u];
__device__ __align__(16) __nv_bfloat16 g_w2d [3][1048576u];
__device__ __align__(16) __nv_bfloat16 g_wkTd[3][1048576u];
__device__ __align__(16) __nv_bfloat16 g_wvTd[2][1048576u];
__device__ __align__(16) __nv_bfloat16 g_w1kd[3][1048576u];
__device__ __align__(16) __nv_bfloat16 g_w1vd[2][1048576u];
__device__ __align__(16) __nv_bfloat16 g_wqmd[3][131072u];

// ---------------- warp-MMA primitives ----------------------------------------
__device__ __forceinline__ void ldsm_x4(uint32_t* r, uint32_t sa) {
    asm volatile("ldmatrix.sync.aligned.m8n8.x4.shared.b16 {%0,%1,%2,%3}, [%4];"
                 : "=r"(r[0]), "=r"(r[1]), "=r"(r[2]), "=r"(r[3]) : "r"(sa));
}
__device__ __forceinline__ void mma16816(float* c, const uint32_t* a, const uint32_t* b) {
    asm volatile("mma.sync.aligned.m16n8k16.row.col.f32.bf16.bf16.f32 "
                 "{%0,%1,%2,%3}, {%4,%5,%6,%7}, {%8,%9}, {%0,%1,%2,%3};"
                 : "+f"(c[0]), "+f"(c[1]), "+f"(c[2]), "+f"(c[3])
                 : "r"(a[0]), "r"(a[1]), "r"(a[2]), "r"(a[3]), "r"(b[0]), "r"(b[1]));
}
__device__ __forceinline__ uint32_t pack_bf2(__nv_bfloat16 a, __nv_bfloat16 b) {
    return (uint32_t)__bfloat16_as_ushort(a) | ((uint32_t)__bfloat16_as_ushort(b) << 16);
}
__device__ __forceinline__ void fsplit3(float x, __nv_bfloat16& a, __nv_bfloat16& b,
                                        __nv_bfloat16& c) {
    a = __float2bfloat16(x);
    float r = x - __bfloat162float(a);
    b = __float2bfloat16(r);
    c = __float2bfloat16(r - __bfloat162float(b));
}

// ---------------- warp-MMA GEMM ----------------------------------------------
#define TROW_B   80
#define TILE_B   (128 * TROW_B)

template<int NDIG>
__global__ __launch_bounds__(256) void mma_gemm(
    int K,
    const __nv_bfloat16* __restrict__ A0, const __nv_bfloat16* __restrict__ A1,
    const __nv_bfloat16* __restrict__ A2,
    const __nv_bfloat16* __restrict__ B0, const __nv_bfloat16* __restrict__ B1,
    const __nv_bfloat16* __restrict__ B2,
    float* __restrict__ C, int ldc,
    const float* __restrict__ colbias,
    const float* __restrict__ addmat, int addld, int relu,
    int wmode)
{
    constexpr int STAGE = 2 * NDIG * TILE_B;
    extern __shared__ char smem[];
    const int tid  = threadIdx.x;
    const int lane = tid & 31;
    const int wid  = tid >> 5;
    const int wm   = wid >> 2;
    const int wn   = wid & 3;
    const int m0   = blockIdx.y * 128;
    const int n0   = blockIdx.x * 128;

    const __nv_bfloat16* src[6] = {A0, A1, A2, B0, B1, B2};
    if (NDIG == 2) { src[2] = B0; src[3] = B1; }
    const int nk = K >> 5;

    auto load_stage = [&](int c, int s) {
#pragma unroll
        for (int it = 0; it < 4 * NDIG; it++) {
            int u   = tid + it * 256;
            int t   = u >> 9;
            int idx = u & 511;
            int row = idx >> 2, ch = idx & 3;
            const __nv_bfloat16* g = src[t]
                + (size_t)(((t < NDIG) ? m0 : n0) + row) * K + c * 32 + ch * 8;
            uint32_t sa = (uint32_t)__cvta_generic_to_shared(
                smem + s * STAGE + t * TILE_B + row * TROW_B + ch * 16);
            asm volatile("cp.async.ca.shared.global [%0], [%1], 16;" :: "r"(sa), "l"(g));
        }
        asm volatile("cp.async.commit_group;" ::: "memory");
    };

    float acc[4][4][4];
#pragma unroll
    for (int i = 0; i < 4; i++)
#pragma unroll
        for (int j = 0; j < 4; j++)
#pragma unroll
            for (int r = 0; r < 4; r++) acc[i][j][r] = 0.f;

    const int a_r  = (lane & 7) + ((lane >> 3) & 1) * 8;
    const int a_cb = (lane >> 4);
    const int b_r  = (lane & 7) + (lane >> 4) * 8;
    const int b_cb = (lane >> 3) & 1;

    load_stage(0, 0);

    for (int c = 0; c < nk; c++) {
        const int s = c & 1;
        if (c + 1 < nk) {
            load_stage(c + 1, s ^ 1);
            asm volatile("cp.async.wait_group 1;" ::: "memory");
        } else {
            asm volatile("cp.async.wait_group 0;" ::: "memory");
        }
        __syncthreads();

        const char* stg = smem + s * STAGE;
#pragma unroll
        for (int ks = 0; ks < 2; ks++) {
            uint32_t bfr[NDIG][4][2];
#pragma unroll
            for (int db = 0; db < NDIG; db++) {
                const char* tb = stg + (NDIG + db) * TILE_B;
#pragma unroll
                for (int jp = 0; jp < 2; jp++) {
                    int row = wn * 32 + jp * 16 + b_r;
                    uint32_t rr[4];
                    ldsm_x4(rr, (uint32_t)__cvta_generic_to_shared(
                        tb + row * TROW_B + (ks * 2 + b_cb) * 16));
                    bfr[db][jp * 2 + 0][0] = rr[0]; bfr[db][jp * 2 + 0][1] = rr[1];
                    bfr[db][jp * 2 + 1][0] = rr[2]; bfr[db][jp * 2 + 1][1] = rr[3];
                }
            }
#pragma unroll
            for (int da = 0; da < NDIG; da++) {
                uint32_t a[4][4];
                const char* ta = stg + da * TILE_B;
#pragma unroll
                for (int i = 0; i < 4; i++) {
                    int row = wm * 64 + i * 16 + a_r;
                    ldsm_x4(a[i], (uint32_t)__cvta_generic_to_shared(
                        ta + row * TROW_B + (ks * 2 + a_cb) * 16));
                }
#pragma unroll
                for (int db = 0; db < NDIG; db++) {
                    if (da + db >= NDIG) break;
#pragma unroll
                    for (int i = 0; i < 4; i++)
#pragma unroll
                        for (int j = 0; j < 4; j++)
                            mma16816(acc[i][j], a[i], bfr[db][j]);
                }
            }
        }
        __syncthreads();
    }

    auto emit = [&](int r, int col, float v0, float v1) {
        if (wmode == 1 || wmode == 2) {
            int h, d, co;
            if (wmode == 1) { h = col >> 7; d = col & 127; co = h * 192 + d; }
            else            { h = col >> 6; d = col & 63;  co = h * 192 + 128 + d; }
            v0 += colbias[co]; v1 += colbias[co + 1];
            *(float2*)(C + (size_t)r * 3072 + co) = make_float2(v0, v1);
            return;
        }
        if (wmode == 4) {
            int s = r >> 2, b = r & 3;
            const float* am = addmat + (size_t)s * addld + col;
            v0 = fmaxf(v0 + am[0], 0.f);
            v1 = fmaxf(v1 + am[1], 0.f);
            *(float2*)(C + (size_t)(b * 2048 + s) * 1024 + col) = make_float2(v0, v1);
            return;
        }
        if (colbias) { v0 += colbias[col]; v1 += colbias[col + 1]; }
        if (addmat) {
            const float* am = addmat + (size_t)(r & (S_ - 1)) * addld + col;
            v0 += am[0]; v1 += am[1];
        }
        if (relu) { v0 = fmaxf(v0, 0.f); v1 = fmaxf(v1, 0.f); }
        *(float2*)(C + (size_t)r * ldc + col) = make_float2(v0, v1);
    };

#pragma unroll
    for (int i = 0; i < 4; i++) {
        int row = m0 + wm * 64 + i * 16 + (lane >> 2);
#pragma unroll
        for (int j = 0; j < 4; j++) {
            int col = n0 + wn * 32 + j * 8 + (lane & 3) * 2;
            emit(row,     col, acc[i][j][0], acc[i][j][1]);
            emit(row + 8, col, acc[i][j][2], acc[i][j][3]);
        }
    }
}

// ---------------- mma flash attention (64q x 64k tiles, 2-digit bf16) --------
#define AP  72
#define ATB (64 * AP * 2)

__global__ __launch_bounds__(128) void attn_mma(
    const float* __restrict__ qkv, const int* __restrict__ seltok,
    int nkeys, int winstart, float* __restrict__ outb)
{
    extern __shared__ char smem[];
    char* Qd[2] = { smem,            smem + ATB     };
    char* Kd[2] = { smem + 2 * ATB,  smem + 3 * ATB };
    char* Vt[2] = { smem + 4 * ATB,  smem + 5 * ATB };
    char* Pd[2] = { smem + 6 * ATB,  smem + 7 * ATB };

    const int tid  = threadIdx.x;
    const int lane = tid & 31;
    const int wid  = tid >> 5;
    const int bh   = blockIdx.y;
    const int b    = bh >> 4, h = bh & 15;
    const int q0   = blockIdx.x * 64;

    const int a_r  = (lane & 7) + ((lane >> 3) & 1) * 8;
    const int a_cb = (lane >> 4);
    const int b_r  = (lane & 7) + (lane >> 4) * 8;
    const int b_cb = (lane >> 3) & 1;

#pragma unroll
    for (int i = 0; i < 8; i++) {
        int idx = tid + i * 128;
        int r = idx >> 4, ch = idx & 15;
        float4 v = *(const float4*)(qkv + (size_t)(q0 + r) * 12288 + b * 3072 + h * 192 + ch * 4);
        __nv_bfloat16 h0 = __float2bfloat16(v.x), h1 = __float2bfloat16(v.y);
        __nv_bfloat16 h2 = __float2bfloat16(v.z), h3 = __float2bfloat16(v.w);
        *(uint2*)(Qd[0] + r * (AP*2) + ch * 8) = make_uint2(pack_bf2(h0,h1), pack_bf2(h2,h3));
        __nv_bfloat16 e0 = __float2bfloat16(v.x - __bfloat162float(h0));
        __nv_bfloat16 e1 = __float2bfloat16(v.y - __bfloat162float(h1));
        __nv_bfloat16 e2 = __float2bfloat16(v.z - __bfloat162float(h2));
        __nv_bfloat16 e3 = __float2bfloat16(v.w - __bfloat162float(h3));
        *(uint2*)(Qd[1] + r * (AP*2) + ch * 8) = make_uint2(pack_bf2(e0,e1), pack_bf2(e2,e3));
    }
    __syncthreads();

    float m[2] = {-3.0e38f, -3.0e38f};
    float l[2] = {0.f, 0.f};
    float o[8][4];
#pragma unroll
    for (int j = 0; j < 8; j++)
#pragma unroll
        for (int r = 0; r < 4; r++) o[j][r] = 0.f;

    const int ntiles = nkeys >> 6;
    for (int kt = 0; kt < ntiles; kt++) {
#pragma unroll
        for (int i = 0; i < 8; i++) {
            int idx = tid + i * 128;
            int r = idx >> 4, ch = idx & 15;
            int tok = seltok ? seltok[b * 1024 + kt * 64 + r] : (winstart + kt * 64 + r);
            float4 v = *(const float4*)(qkv + (size_t)tok * 12288 + b * 3072 + h * 192 + 64 + ch * 4);
            __nv_bfloat16 h0 = __float2bfloat16(v.x), h1 = __float2bfloat16(v.y);
            __nv_bfloat16 h2 = __float2bfloat16(v.z), h3 = __float2bfloat16(v.w);
            *(uint2*)(Kd[0] + r * (AP*2) + ch * 8) = make_uint2(pack_bf2(h0,h1), pack_bf2(h2,h3));
            __nv_bfloat16 e0 = __float2bfloat16(v.x - __bfloat162float(h0));
            __nv_bfloat16 e1 = __float2bfloat16(v.y - __bfloat162float(h1));
            __nv_bfloat16 e2 = __float2bfloat16(v.z - __bfloat162float(h2));
            __nv_bfloat16 e3 = __float2bfloat16(v.w - __bfloat162float(h3));
            *(uint2*)(Kd[1] + r * (AP*2) + ch * 8) = make_uint2(pack_bf2(e0,e1), pack_bf2(e2,e3));
        }
#pragma unroll
        for (int i = 0; i < 8; i++) {
            int idx = tid + i * 128;
            int r = idx & 63, ch = idx >> 6;
            int tok = seltok ? seltok[b * 1024 + kt * 64 + r] : (winstart + kt * 64 + r);
            float4 v = *(const float4*)(qkv + (size_t)tok * 12288 + b * 3072 + h * 192 + 128 + ch * 4);
            float vv[4] = {v.x, v.y, v.z, v.w};
#pragma unroll
            for (int jj = 0; jj < 4; jj++) {
                __nv_bfloat16 h0 = __float2bfloat16(vv[jj]);
                __nv_bfloat16 e0 = __float2bfloat16(vv[jj] - __bfloat162float(h0));
                *(__nv_bfloat16*)(Vt[0] + (ch * 4 + jj) * (AP*2) + r * 2) = h0;
                *(__nv_bfloat16*)(Vt[1] + (ch * 4 + jj) * (AP*2) + r * 2) = e0;
            }
        }
        __syncthreads();

        float sc[8][4];
#pragma unroll
        for (int j = 0; j < 8; j++)
#pragma unroll
            for (int r = 0; r < 4; r++) sc[j][r] = 0.f;

#pragma unroll
        for (int pr = 0; pr < 3; pr++) {
            const int da = (pr == 2) ? 1 : 0;
            const int db = (pr == 1) ? 1 : 0;
#pragma unroll
            for (int ks = 0; ks < 4; ks++) {
                uint32_t a[4];
                ldsm_x4(a, (uint32_t)__cvta_generic_to_shared(
                    Qd[da] + (wid * 16 + a_r) * (AP*2) + (ks * 2 + a_cb) * 16));
                uint32_t bb[8][2];
#pragma unroll
                for (int jp = 0; jp < 4; jp++) {
                    uint32_t rr[4];
                    ldsm_x4(rr, (uint32_t)__cvta_generic_to_shared(
                        Kd[db] + (jp * 16 + b_r) * (AP*2) + (ks * 2 + b_cb) * 16));
                    bb[jp*2+0][0] = rr[0]; bb[jp*2+0][1] = rr[1];
                    bb[jp*2+1][0] = rr[2]; bb[jp*2+1][1] = rr[3];
                }
#pragma unroll
                for (int j = 0; j < 8; j++) mma16816(sc[j], a, bb[j]);
            }
        }

        float mx0 = -3.0e38f, mx1 = -3.0e38f;
#pragma unroll
        for (int j = 0; j < 8; j++) {
#pragma unroll
            for (int r = 0; r < 4; r++) sc[j][r] *= SCALE_;
            mx0 = fmaxf(mx0, fmaxf(sc[j][0], sc[j][1]));
            mx1 = fmaxf(mx1, fmaxf(sc[j][2], sc[j][3]));
        }
        mx0 = fmaxf(mx0, __shfl_xor_sync(0xffffffffu, mx0, 1));
        mx0 = fmaxf(mx0, __shfl_xor_sync(0xffffffffu, mx0, 2));
        mx1 = fmaxf(mx1, __shfl_xor_sync(0xffffffffu, mx1, 1));
        mx1 = fmaxf(mx1, __shfl_xor_sync(0xffffffffu, mx1, 2));
        float mn0 = fmaxf(m[0], mx0), mn1 = fmaxf(m[1], mx1);
        float corr0 = __expf(m[0] - mn0), corr1 = __expf(m[1] - mn1);

        const int prow0 = wid * 16 + (lane >> 2);
        const int pcol  = (lane & 3) * 2;
        float sum0 = 0.f, sum1 = 0.f;
#pragma unroll
        for (int j = 0; j < 8; j++) {
            float p00 = __expf(sc[j][0] - mn0);
            float p01 = __expf(sc[j][1] - mn0);
            float p10 = __expf(sc[j][2] - mn1);
            float p11 = __expf(sc[j][3] - mn1);
            sum0 += p00 + p01; sum1 += p10 + p11;
            __nv_bfloat16 a0 = __float2bfloat16(p00), a1 = __float2bfloat16(p01);
            __nv_bfloat16 b0 = __float2bfloat16(p10), b1 = __float2bfloat16(p11);
            int c0 = j * 8 + pcol;
            *(uint32_t*)(Pd[0] + prow0 * (AP*2) + c0 * 2)       = pack_bf2(a0, a1);
            *(uint32_t*)(Pd[0] + (prow0 + 8) * (AP*2) + c0 * 2) = pack_bf2(b0, b1);
            __nv_bfloat16 ae0 = __float2bfloat16(p00 - __bfloat162float(a0));
            __nv_bfloat16 ae1 = __float2bfloat16(p01 - __bfloat162float(a1));
            __nv_bfloat16 be0 = __float2bfloat16(p10 - __bfloat162float(b0));
            __nv_bfloat16 be1 = __float2bfloat16(p11 - __bfloat162float(b1));
            *(uint32_t*)(Pd[1] + prow0 * (AP*2) + c0 * 2)       = pack_bf2(ae0, ae1);
            *(uint32_t*)(Pd[1] + (prow0 + 8) * (AP*2) + c0 * 2) = pack_bf2(be0, be1);
        }
        sum0 += __shfl_xor_sync(0xffffffffu, sum0, 1);
        sum0 += __shfl_xor_sync(0xffffffffu, sum0, 2);
        sum1 += __shfl_xor_sync(0xffffffffu, sum1, 1);
        sum1 += __shfl_xor_sync(0xffffffffu, sum1, 2);
        l[0] = l[0] * corr0 + sum0; m[0] = mn0;
        l[1] = l[1] * corr1 + sum1; m[1] = mn1;
#pragma unroll
        for (int j = 0; j < 8; j++) {
            o[j][0] *= corr0; o[j][1] *= corr0;
            o[j][2] *= corr1; o[j][3] *= corr1;
        }
        __syncthreads();

#pragma unroll
        for (int pr = 0; pr < 3; pr++) {
            const int da = (pr == 2) ? 1 : 0;
            const int db = (pr == 1) ? 1 : 0;
#pragma unroll
            for (int ks = 0; ks < 4; ks++) {
                uint32_t a[4];
                ldsm_x4(a, (uint32_t)__cvta_generic_to_shared(
                    Pd[da] + (wid * 16 + a_r) * (AP*2) + (ks * 2 + a_cb) * 16));
                uint32_t bb[8][2];
#pragma unroll
                for (int jp = 0; jp < 4; jp++) {
                    uint32_t rr[4];
                    ldsm_x4(rr, (uint32_t)__cvta_generic_to_shared(
                        Vt[db] + (jp * 16 + b_r) * (AP*2) + (ks * 2 + b_cb) * 16));
                    bb[jp*2+0][0] = rr[0]; bb[jp*2+0][1] = rr[1];
                    bb[jp*2+1][0] = rr[2]; bb[jp*2+1][1] = rr[3];
                }
#pragma unroll
                for (int j = 0; j < 8; j++) mma16816(o[j], a, bb[j]);
            }
        }
        __syncthreads();
    }

    const float inv0 = 1.f / l[0], inv1 = 1.f / l[1];
    const int row0 = q0 + wid * 16 + (lane >> 2);
#pragma unroll
    for (int j = 0; j < 8; j++) {
        int col = h * 64 + j * 8 + (lane & 3) * 2;
        *(float2*)(outb + (size_t)(b * S_ + row0) * 1024 + col) =
            make_float2(o[j][0] * inv0, o[j][1] * inv0);
        *(float2*)(outb + (size_t)(b * S_ + row0 + 8) * 1024 + col) =
            make_float2(o[j][2] * inv1, o[j][3] * inv1);
    }
}

// ---------------- split / prep kernels ---------------------------------------
__global__ void split3k(const float* __restrict__ s,
                        __nv_bfloat16* __restrict__ d0, __nv_bfloat16* __restrict__ d1,
                        __nv_bfloat16* __restrict__ d2, int n)
{
    int i = blockIdx.x * 256 + threadIdx.x;
    if (i >= n) return;
    __nv_bfloat16 a, b, c;
    fsplit3(s[i], a, b, c);
    d0[i] = a; d1[i] = b; d2[i] = c;
}

__global__ void split2k(const float* __restrict__ s,
                        __nv_bfloat16* __restrict__ d0, __nv_bfloat16* __restrict__ d1, int n)
{
    int i = blockIdx.x * 256 + threadIdx.x;
    if (i >= n) return;
    float x = s[i];
    __nv_bfloat16 a = __float2bfloat16(x);
    d0[i] = a;
    d1[i] = __float2bfloat16(x - __bfloat162float(a));
}

__global__ void prep_wqk(const float* __restrict__ w_qkv)
{
    int idx = blockIdx.x * 256 + threadIdx.x;
    int r = idx >> 10, k = idx & 1023;
    int h = r >> 7, d = r & 127;
    float x = w_qkv[(size_t)(h * 192 + d) * 1024 + k];
    __nv_bfloat16 a, b, c;
    fsplit3(x, a, b, c);
    g_wqkd[0][idx] = a; g_wqkd[1][idx] = b; g_wqkd[2][idx] = c;
}

__global__ void prep_wqm(const float* __restrict__ w_qkv)
{
    int idx = blockIdx.x * 256 + threadIdx.x;
    if (idx >= 131072) return;
    int d = idx >> 10, k = idx & 1023;
    float v = 0.f;
    if (d < 64) {
#pragma unroll
        for (int h = 0; h < H_; h++) v += w_qkv[(size_t)(h * 192 + d) * 1024 + k];
        v *= (1.f / (float)H_);
    }
    __nv_bfloat16 a, b, c;
    fsplit3(v, a, b, c);
    g_wqmd[0][idx] = a; g_wqmd[1][idx] = b; g_wqmd[2][idx] = c;
}

__global__ void prep_bqm(const float* __restrict__ b_qkv)
{
    int d = threadIdx.x;
    float v = 0.f;
    if (d < 64) {
#pragma unroll
        for (int h = 0; h < H_; h++) v += b_qkv[h * 192 + d];
        v *= (1.f / (float)H_);
    }
    g_bqm[d] = v;
}

__global__ void qm2cvt()
{
    int idx = blockIdx.x * 256 + threadIdx.x;
    if (idx >= 8192 * 64) return;
    int r = idx >> 6, d = idx & 63;
    int s = r >> 2, b = r & 3;
    g_qm2d[((size_t)(b * 2048 + s)) * 64 + d] = (double)g_qm2f[(size_t)r * 128 + d];
}

__global__ void prep_wv(const float* __restrict__ w_qkv)
{
    int idx = blockIdx.x * 256 + threadIdx.x;
    int r = idx >> 10, k = idx & 1023;
    int h = r >> 6, d = r & 63;
    float x = w_qkv[(size_t)(h * 192 + 128 + d) * 1024 + k];
    __nv_bfloat16 a = __float2bfloat16(x);
    g_wvd[0][idx] = a;
    g_wvd[1][idx] = __float2bfloat16(x - __bfloat162float(a));
}

__global__ __launch_bounds__(256) void prep_wkT(const float* __restrict__ w_qkv)
{
    __shared__ float tile[32][33];
    int cb = blockIdx.x * 32, db = blockIdx.y * 32;
    int tx = threadIdx.x & 31, ty = threadIdx.x >> 5;
    for (int i = ty; i < 32; i += 8) {
        int d = db + i, h = d >> 6, dd = d & 63;
        tile[i][tx] = w_qkv[(size_t)(h * 192 + 64 + dd) * 1024 + cb + tx];
    }
    __syncthreads();
    for (int i = ty; i < 32; i += 8) {
        int c = cb + i, d = db + tx;
        __nv_bfloat16 a, b, cc;
        fsplit3(tile[tx][i], a, b, cc);
        size_t off = (size_t)c * 1024 + d;
        g_wkTd[0][off] = a; g_wkTd[1][off] = b; g_wkTd[2][off] = cc;
    }
}

__global__ __launch_bounds__(256) void prep_wvT(const float* __restrict__ w_qkv)
{
    __shared__ float tile[32][33];
    int cb = blockIdx.x * 32, db = blockIdx.y * 32;
    int tx = threadIdx.x & 31, ty = threadIdx.x >> 5;
    for (int i = ty; i < 32; i += 8) {
        int d = db + i, h = d >> 6, dd = d & 63;
        tile[i][tx] = w_qkv[(size_t)(h * 192 + 128 + dd) * 1024 + cb + tx];
    }
    __syncthreads();
    for (int i = ty; i < 32; i += 8) {
        int c = cb + i, d = db + tx;
        float x = tile[tx][i];
        __nv_bfloat16 a = __float2bfloat16(x);
        size_t off = (size_t)c * 1024 + d;
        g_wvTd[0][off] = a;
        g_wvTd[1][off] = __float2bfloat16(x - __bfloat162float(a));
    }
}

__global__ void prep_w1d(const float* __restrict__ w_c1)
{
    int idx = blockIdx.x * 256 + threadIdx.x;
    int n = idx >> 10, k = idx & 1023;
    __nv_bfloat16 a, b, c;
    fsplit3(w_c1[n * 1027 + k], a, b, c);
    g_w1d[0][idx] = a; g_w1d[1][idx] = b; g_w1d[2][idx] = c;
}

__global__ void prep_padd(const float* __restrict__ w_c1,
                          const float* __restrict__ b_c1,
                          const float* __restrict__ pos)
{
    int idx = blockIdx.x * 256 + threadIdx.x;
    int s = idx >> 10, n = idx & 1023;
    const float* wr = w_c1 + n * 1027 + 1024;
    g_padd[idx] = b_c1[n] + wr[0]*pos[s*3] + wr[1]*pos[s*3+1] + wr[2]*pos[s*3+2];
}

// ---------------- aux kernels -------------------------------------------------
__global__ void cmp_reduce_one(const float* __restrict__ src, float* __restrict__ dst)
{
    int idx = blockIdx.x * 256 + threadIdx.x;
    if (idx >= B_ * NB_ * 1024) return;
    int c = idx & 1023;
    int n = (idx >> 10) % NB_;
    int b = idx / (NB_ * 1024);
    float s = 0.f;
    size_t base = (size_t)(b * S_ + n * 16) * 1024 + c;
#pragma unroll 8
    for (int j = 0; j < 32; j++) s += src[base + (size_t)j * 1024];
    dst[(size_t)(b * NB_ + n) * 1024 + c] = s * (1.f / 32.f);
}

__global__ __launch_bounds__(256) void calc_qm1(const float* __restrict__ qkv)
{
    int bh = blockIdx.x;
    int b = bh >> 4, h = bh & 15;
    int tid = threadIdx.x;
    int strip = tid >> 6, d = tid & 63;
    float a = 0.f;
    size_t off = (size_t)b * 3072 + h * 192 + d;
    for (int t = strip * 512; t < (strip + 1) * 512; t++)
        a += qkv[(size_t)t * 12288 + off];
    __shared__ float red[256];
    red[tid] = a; __syncthreads();
    if (strip == 0)
        g_qm1[bh * 64 + d] = (red[d] + red[64 + d] + red[128 + d] + red[192 + d])
                             * (1.f / (float)S_);
}

__global__ void calc_ckm()
{
    int idx = blockIdx.x * 256 + threadIdx.x;
    if (idx >= B_ * NB_ * 64) return;
    int d = idx & 63;
    int n = (idx >> 6) % NB_;
    int b = idx / (NB_ * 64);
    double a = 0.0;
    size_t base = (size_t)(b * NB_ + n) * 1024 + d;
#pragma unroll
    for (int h = 0; h < H_; h++) a += (double)g_cmpk[base + h * 64];
    g_ckmd[idx] = a * (1.0 / (double)H_);
}

__global__ __launch_bounds__(128) void outcmp_kernel()
{
    int bh = blockIdx.x;
    int b = bh >> 4, h = bh & 15;
    int tid = threadIdx.x;
    __shared__ float qs[64], p[128], red[128];
    if (tid < 64) qs[tid] = g_qm1[bh * 64 + tid];
    __syncthreads();
    float sc = -3.0e38f;
    if (tid < NB_) {
        const float* kr = &g_cmpk[(size_t)(b * NB_ + tid) * 1024 + h * 64];
        float dot = 0.f;
#pragma unroll
        for (int d = 0; d < 64; d++) dot += qs[d] * kr[d];
        sc = dot * SCALE_;
    }
    red[tid] = sc; __syncthreads();
    for (int off = 64; off; off >>= 1) { if (tid < off) red[tid] = fmaxf(red[tid], red[tid + off]); __syncthreads(); }
    float mx = red[0]; __syncthreads();
    float e = (tid < NB_) ? __expf(sc - mx) : 0.f;
    p[tid] = e;
    red[tid] = e; __syncthreads();
    for (int off = 64; off; off >>= 1) { if (tid < off) red[tid] += red[tid + off]; __syncthreads(); }
    float inv = 1.f / red[0];
    if (tid < 64) {
        float a = 0.f;
        for (int n = 0; n < NB_; n++)
            a += p[n] * g_cmpv[(size_t)(b * NB_ + n) * 1024 + h * 64 + tid];
        g_outcmp[bh * 64 + tid] = a * inv;
    }
}

__global__ __launch_bounds__(128) void imp_probs8()
{
    extern __shared__ double sh[];
    double* cks = sh;
    double* qs  = sh + 127 * 65;
    __shared__ double red[128];
    const int b  = blockIdx.y;
    const int s0 = blockIdx.x * 8;
    const int tid = threadIdx.x;

    for (int i = tid; i < NB_ * 64; i += 128) {
        int n = i >> 6, d = i & 63;
        cks[n * 65 + d] = g_ckmd[((size_t)b * NB_ + n) * 64 + d];
    }
    for (int i = tid; i < 8 * 64; i += 128)
        qs[i] = g_qm2d[((size_t)(b * 2048 + s0)) * 64 + i];
    __syncthreads();

    for (int ss = 0; ss < 8; ss++) {
        double sc = -1.0e300;
        if (tid < NB_) {
            const double* kr = &cks[tid * 65];
            const double* qq = &qs[ss * 64];
            double dot = 0.0;
#pragma unroll
            for (int d = 0; d < 64; d++) dot += qq[d] * kr[d];
            sc = dot * 0.125;
        }
        red[tid] = sc; __syncthreads();
        for (int off = 64; off; off >>= 1) { if (tid < off) red[tid] = fmax(red[tid], red[tid + off]); __syncthreads(); }
        double mx = red[0]; __syncthreads();
        double e = (tid < NB_) ? exp(sc - mx) : 0.0;
        red[tid] = e; __syncthreads();
        for (int off = 64; off; off >>= 1) { if (tid < off) red[tid] += red[tid + off]; __syncthreads(); }
        double inv = 1.0 / red[0];
        if (tid < NB_) g_probs[((size_t)(b * 2048 + s0 + ss)) * NB_ + tid] = e * inv;
        __syncthreads();
    }
}

__global__ __launch_bounds__(128) void imp_reduce()
{
    int blk = blockIdx.x;
    if (blk >= B_ * NB_) return;
    int b = blk / NB_, n = blk % NB_;
    int tid = threadIdx.x;
    __shared__ double red[128];
    double a = 0.0;
    for (int s = tid; s < S_; s += 128)
        a += g_probs[(size_t)(b * S_ + s) * NB_ + n];
    red[tid] = a; __syncthreads();
    for (int off = 64; off; off >>= 1) {
        if (tid < off) red[tid] += red[tid + off];
        __syncthreads();
    }
    if (tid == 0) g_imp[blk] = red[0] * (1.0 / (double)S_);
}

__global__ __launch_bounds__(128) void topk_sel()
{
    int b = blockIdx.x, tid = threadIdx.x;
    __shared__ double vals[NB_];
    __shared__ int    sb[NUM_SEL_];
    if (tid < NB_) vals[tid] = g_imp[b * NB_ + tid];
    __syncthreads();
    if (tid == 0) {
        for (int i = 0; i < NUM_SEL_; i++) {
            int bi = 0; double bv = vals[0];
            for (int n = 1; n < NB_; n++) if (vals[n] > bv) { bv = vals[n]; bi = n; }
            sb[i] = bi; vals[bi] = -1.0e300;
        }
    }
    __syncthreads();
    for (int j = tid; j < NUM_SEL_ * SEL_BLK_; j += 128) {
        int t = sb[j >> 6] * SEL_BLK_ + (j & 63);
        if (t > S_ - 1) t = S_ - 1;
        g_seltok[b * 1024 + j] = t;
    }
}

__global__ __launch_bounds__(128) void gate_combine(
    const float* __restrict__ w_g, const float* __restrict__ b_g,
    float* __restrict__ out)
{
    int bs = blockIdx.x;
    int b = bs >> 11;
    int tid = threadIdx.x;
    size_t base = (size_t)bs * 1024;
    float a0 = 0.f, a1 = 0.f, a2 = 0.f;
    for (int c = tid; c < 3072; c += 128) {
        float v;
        if (c < 1024)       v = g_outcmp[(b * 16 + (c >> 6)) * 64 + (c & 63)];
        else if (c < 2048)  v = g_oslc[base + c - 1024];
        else                v = g_owin[base + c - 2048];
        a0 += v * w_g[c];
        a1 += v * w_g[3072 + c];
        a2 += v * w_g[6144 + c];
    }
    __shared__ float r0[128], r1[128], r2[128];
    __shared__ float gg[3];
    r0[tid] = a0; r1[tid] = a1; r2[tid] = a2; __syncthreads();
    for (int off = 64; off; off >>= 1) {
        if (tid < off) { r0[tid] += r0[tid+off]; r1[tid] += r1[tid+off]; r2[tid] += r2[tid+off]; }
        __syncthreads();
    }
    if (tid == 0) {
        float l0 = r0[0] + b_g[0], l1 = r1[0] + b_g[1], l2 = r2[0] + b_g[2];
        float mx = fmaxf(l0, fmaxf(l1, l2));
        float e0 = __expf(l0 - mx), e1 = __expf(l1 - mx), e2 = __expf(l2 - mx);
        float inv = 1.f / (e0 + e1 + e2);
        gg[0] = e0 * inv; gg[1] = e1 * inv; gg[2] = e2 * inv;
    }
    __syncthreads();
    float gv0 = gg[0], gv1 = gg[1], gv2 = gg[2];
    for (int c = tid; c < 1024; c += 128) {
        float oc = g_outcmp[(b * 16 + (c >> 6)) * 64 + (c & 63)];
        out[base + c] = gv0 * oc + gv1 * g_oslc[base + c] + gv2 * g_owin[base + c];
    }
}

// ---------------- launch -----------------------------------------------------
extern "C" void kernel_launch(void* const* d_in, const int* in_sizes, int n_in,
                              void* d_out, int out_size)
{
    const float* x     = (const float*)d_in[0];
    const float* pos   = (const float*)d_in[1];
    const float* w_qkv = (const float*)d_in[2];
    const float* b_qkv = (const float*)d_in[3];
    const float* w_c1  = (const float*)d_in[4];
    const float* b_c1  = (const float*)d_in[5];
    const float* w_c2  = (const float*)d_in[6];
    const float* b_c2  = (const float*)d_in[7];
    const float* w_g   = (const float*)d_in[8];
    const float* b_g   = (const float*)d_in[9];
    float* out = (float*)d_out;
    (void)in_sizes; (void)n_in; (void)out_size;

    void *p_qkv, *p_padd, *p_sel, *p_oslc, *p_owin, *p_rk, *p_rv, *p_rkm, *p_rvm;
    void *p_cmpk, *p_cmpv, *p_w1k, *p_w1v, *p_qm2f, *p_bqm;
    cudaGetSymbolAddress(&p_qkv,  g_qkv);
    cudaGetSymbolAddress(&p_padd, g_padd);
    cudaGetSymbolAddress(&p_sel,  g_seltok);
    cudaGetSymbolAddress(&p_oslc, g_oslc);
    cudaGetSymbolAddress(&p_owin, g_owin);
    cudaGetSymbolAddress(&p_rk,   g_rk);
    cudaGetSymbolAddress(&p_rv,   g_rv);
    cudaGetSymbolAddress(&p_rkm,  g_rkm);
    cudaGetSymbolAddress(&p_rvm,  g_rvm);
    cudaGetSymbolAddress(&p_cmpk, g_cmpk);
    cudaGetSymbolAddress(&p_cmpv, g_cmpv);
    cudaGetSymbolAddress(&p_w1k,  g_w1k);
    cudaGetSymbolAddress(&p_w1v,  g_w1v);
    cudaGetSymbolAddress(&p_qm2f, g_qm2f);
    cudaGetSymbolAddress(&p_bqm,  g_bqm);

    void *p_xd, *p_rkmd, *p_rvmd, *p_wqkd, *p_wvd, *p_w1d, *p_w2d;
    void *p_wkTd, *p_wvTd, *p_w1kd, *p_w1vd, *p_wqmd;
    cudaGetSymbolAddress(&p_xd,   g_xd);
    cudaGetSymbolAddress(&p_rkmd, g_rkmd);
    cudaGetSymbolAddress(&p_rvmd, g_rvmd);
    cudaGetSymbolAddress(&p_wqkd, g_wqkd);
    cudaGetSymbolAddress(&p_wvd,  g_wvd);
    cudaGetSymbolAddress(&p_w1d,  g_w1d);
    cudaGetSymbolAddress(&p_w2d,  g_w2d);
    cudaGetSymbolAddress(&p_wkTd, g_wkTd);
    cudaGetSymbolAddress(&p_wvTd, g_wvTd);
    cudaGetSymbolAddress(&p_w1kd, g_w1kd);
    cudaGetSymbolAddress(&p_w1vd, g_w1vd);
    cudaGetSymbolAddress(&p_wqmd, g_wqmd);

    const size_t BIGN = 8388608u;
    const size_t WQKN = 2097152u;
    const size_t WN   = 1048576u;
    const size_t RMN  = 524288u;
    const size_t WQMN = 131072u;
    __nv_bfloat16* xd   = (__nv_bfloat16*)p_xd;
    __nv_bfloat16* rkmd = (__nv_bfloat16*)p_rkmd;
    __nv_bfloat16* rvmd = (__nv_bfloat16*)p_rvmd;
    __nv_bfloat16* wqkd = (__nv_bfloat16*)p_wqkd;
    __nv_bfloat16* wvd  = (__nv_bfloat16*)p_wvd;
    __nv_bfloat16* w1d  = (__nv_bfloat16*)p_w1d;
    __nv_bfloat16* w2d  = (__nv_bfloat16*)p_w2d;
    __nv_bfloat16* wkTd = (__nv_bfloat16*)p_wkTd;
    __nv_bfloat16* wvTd = (__nv_bfloat16*)p_wvTd;
    __nv_bfloat16* w1kd = (__nv_bfloat16*)p_w1kd;
    __nv_bfloat16* w1vd = (__nv_bfloat16*)p_w1vd;
    __nv_bfloat16* wqmd = (__nv_bfloat16*)p_wqmd;

    const int GS3 = 2 * 6 * TILE_B;
    const int GS2 = 2 * 4 * TILE_B;
    const int ASM = 8 * ATB;
    const int IPS = (127 * 65 + 8 * 64) * 8;
    cudaFuncSetAttribute(mma_gemm<3>, cudaFuncAttributeMaxDynamicSharedMemorySize, GS3);
    cudaFuncSetAttribute(mma_gemm<2>, cudaFuncAttributeMaxDynamicSharedMemorySize, GS2);
    cudaFuncSetAttribute(attn_mma, cudaFuncAttributeMaxDynamicSharedMemorySize, ASM);
    cudaFuncSetAttribute(imp_probs8, cudaFuncAttributeMaxDynamicSharedMemorySize, IPS);

    static cudaStream_t sA = nullptr, sB = nullptr, sC = nullptr;
    static cudaEvent_t e0 = nullptr, eX = nullptr, e1 = nullptr, eV = nullptr,
                       eQm = nullptr, eQm1 = nullptr, eCk = nullptr, eWin = nullptr,
                       eOc = nullptr, eW1d = nullptr;
    if (!sA) {
        cudaStreamCreateWithFlags(&sA, cudaStreamNonBlocking);
        cudaStreamCreateWithFlags(&sB, cudaStreamNonBlocking);
        cudaStreamCreateWithFlags(&sC, cudaStreamNonBlocking);
        cudaEventCreateWithFlags(&e0,   cudaEventDisableTiming);
        cudaEventCreateWithFlags(&eX,   cudaEventDisableTiming);
        cudaEventCreateWithFlags(&e1,   cudaEventDisableTiming);
        cudaEventCreateWithFlags(&eV,   cudaEventDisableTiming);
        cudaEventCreateWithFlags(&eQm,  cudaEventDisableTiming);
        cudaEventCreateWithFlags(&eQm1, cudaEventDisableTiming);
        cudaEventCreateWithFlags(&eCk,  cudaEventDisableTiming);
        cudaEventCreateWithFlags(&eWin, cudaEventDisableTiming);
        cudaEventCreateWithFlags(&eOc,  cudaEventDisableTiming);
        cudaEventCreateWithFlags(&eW1d, cudaEventDisableTiming);
    }

    // fork root
    cudaEventRecord(e0, 0);

    // s0: x split + qk projection (3-product) + qm1
    split3k<<<32768, 256>>>(x, xd, xd + BIGN, xd + 2*BIGN, 8388608);
    cudaEventRecord(eX, 0);
    prep_wqk<<<8192, 256>>>(w_qkv);
    mma_gemm<2><<<dim3(16, 64), 256, GS2>>>(1024,
        xd, xd + BIGN, nullptr,
        wqkd, wqkd + WQKN, nullptr,
        (float*)p_qkv, 3072, b_qkv, nullptr, 0, 0, 1);
    cudaEventRecord(e1, 0);
    calc_qm1<<<64, 256>>>((const float*)p_qkv);
    cudaEventRecord(eQm1, 0);

    // sA: qm2 fold chain (off critical path), then window attention
    cudaStreamWaitEvent(sA, e0, 0);
    prep_wqm<<<512, 256, 0, sA>>>(w_qkv);
    prep_bqm<<<1, 128, 0, sA>>>(b_qkv);
    cudaStreamWaitEvent(sA, eX, 0);
    mma_gemm<3><<<dim3(1, 64), 256, GS3, sA>>>(1024,
        xd, xd + BIGN, xd + 2*BIGN,
        wqmd, wqmd + WQMN, wqmd + 2*WQMN,
        (float*)p_qm2f, 128, (const float*)p_bqm, nullptr, 0, 0, 0);
    qm2cvt<<<2048, 256, 0, sA>>>();
    cudaEventRecord(eQm, sA);

    // sB: weight prep -> W1K -> fused k-L1 chain -> ckm
    cudaStreamWaitEvent(sB, e0, 0);
    prep_padd<<<8192, 256, 0, sB>>>(w_c1, b_c1, pos);
    prep_w1d<<<4096, 256, 0, sB>>>(w_c1);
    split3k<<<4096, 256, 0, sB>>>(w_c2, w2d, w2d + WN, w2d + 2*WN, 1048576);
    cudaEventRecord(eW1d, sB);
    prep_wkT<<<dim3(32, 32), 256, 0, sB>>>(w_qkv);
    mma_gemm<3><<<dim3(8, 8), 256, GS3, sB>>>(1024,
        w1d, w1d + WN, w1d + 2*WN,
        wkTd, wkTd + WN, wkTd + 2*WN,
        (float*)p_w1k, 1024, nullptr, nullptr, 0, 0, 0);
    split3k<<<4096, 256, 0, sB>>>((const float*)p_w1k, w1kd, w1kd + WN, w1kd + 2*WN, 1048576);
    cudaStreamWaitEvent(sB, eX, 0);
    mma_gemm<3><<<dim3(8, 64), 256, GS3, sB>>>(1024,
        xd, xd + BIGN, xd + 2*BIGN,
        w1kd, w1kd + WN, w1kd + 2*WN,
        (float*)p_rk, 1024, nullptr, (const float*)p_padd, 1024, 1, 4);
    cmp_reduce_one<<<2032, 256, 0, sB>>>((const float*)p_rk, (float*)p_rkm);
    split3k<<<2048, 256, 0, sB>>>((const float*)p_rkm, rkmd, rkmd + RMN, rkmd + 2*RMN, 524288);
    mma_gemm<3><<<dim3(8, 4), 256, GS3, sB>>>(1024,
        rkmd, rkmd + RMN, rkmd + 2*RMN,
        w2d, w2d + WN, w2d + 2*WN,
        (float*)p_cmpk, 1024, b_c2, nullptr, 0, 0, 0);
    calc_ckm<<<127, 256, 0, sB>>>();
    cudaEventRecord(eCk, sB);

    // sC: v projection + fused v-L1 chain + outcmp
    cudaStreamWaitEvent(sC, e0, 0);
    prep_wv <<<4096, 256, 0, sC>>>(w_qkv);
    prep_wvT<<<dim3(32, 32), 256, 0, sC>>>(w_qkv);
    cudaStreamWaitEvent(sC, eX, 0);
    mma_gemm<2><<<dim3(8, 64), 256, GS2, sC>>>(1024,
        xd, xd + BIGN, nullptr,
        wvd, wvd + WN, nullptr,
        (float*)p_qkv, 3072, b_qkv, nullptr, 0, 0, 2);
    cudaEventRecord(eV, sC);
    cudaStreamWaitEvent(sC, eW1d, 0);
    mma_gemm<2><<<dim3(8, 8), 256, GS2, sC>>>(1024,
        w1d, w1d + WN, nullptr,
        wvTd, wvTd + WN, nullptr,
        (float*)p_w1v, 1024, nullptr, nullptr, 0, 0, 0);
    split2k<<<4096, 256, 0, sC>>>((const float*)p_w1v, w1vd, w1vd + WN, 1048576);
    mma_gemm<2><<<dim3(8, 64), 256, GS2, sC>>>(1024,
        xd, xd + BIGN, nullptr,
        w1vd, w1vd + WN, nullptr,
        (float*)p_rv, 1024, nullptr, (const float*)p_padd, 1024, 1, 4);
    cmp_reduce_one<<<2032, 256, 0, sC>>>((const float*)p_rv, (float*)p_rvm);
    split2k<<<2048, 256, 0, sC>>>((const float*)p_rvm, rvmd, rvmd + RMN, 524288);
    mma_gemm<2><<<dim3(8, 4), 256, GS2, sC>>>(1024,
        rvmd, rvmd + RMN, nullptr,
        w2d, w2d + WN, nullptr,
        (float*)p_cmpv, 1024, b_c2, nullptr, 0, 0, 0);
    cudaStreamWaitEvent(sC, eCk, 0);
    cudaStreamWaitEvent(sC, eQm1, 0);
    outcmp_kernel<<<64, 128, 0, sC>>>();
    cudaEventRecord(eOc, sC);

    // sA: window attention (after qm2 chain; needs q,k + v cols)
    cudaStreamWaitEvent(sA, e1, 0);
    cudaStreamWaitEvent(sA, eV, 0);
    attn_mma<<<dim3(S_ / 64, B_ * H_), 128, ASM, sA>>>(
        (const float*)p_qkv, nullptr, WIN_, S_ - WIN_, (float*)p_owin);
    cudaEventRecord(eWin, sA);

    // s0: importance -> top-k -> selected attention
    cudaStreamWaitEvent((cudaStream_t)0, eCk, 0);
    cudaStreamWaitEvent((cudaStream_t)0, eQm, 0);
    imp_probs8<<<dim3(256, B_), 128, IPS>>>();
    imp_reduce<<<B_ * NB_, 128>>>();
    topk_sel<<<4, 128>>>();
    cudaStreamWaitEvent((cudaStream_t)0, eV, 0);
    attn_mma<<<dim3(S_ / 64, B_ * H_), 128, ASM>>>(
        (const float*)p_qkv, (const int*)p_sel, 1024, 0, (float*)p_oslc);

    // join everything, gate
    cudaStreamWaitEvent((cudaStream_t)0, eWin, 0);
    cudaStreamWaitEvent((cudaStream_t)0, eOc, 0);
    gate_combine<<<8192, 128>>>(w_g, b_g, out);
}